// round 3
// baseline (speedup 1.0000x reference)
#include <cuda_runtime.h>

#define Bq  256
#define Nn  2048
#define Dd  512
#define Hh  8
#define DHh 64
#define NK  2047   // N-1 keys per row

// mask representation: 0 = int8 (1 byte/bool), 1 = int32, 2 = float32
__device__ int g_mask_mode;

__global__ void detect_mask_mode_kernel(const unsigned int* __restrict__ mw) {
    if (threadIdx.x == 0 && blockIdx.x == 0) {
        int all01 = 1, allf = 1;
        for (int i = 0; i < 4096; ++i) {
            unsigned v = mw[i];
            if (v != 0u && v != 1u) all01 = 0;
            if (v != 0u && v != 0x3F800000u) allf = 0;
        }
        g_mask_mode = all01 ? 1 : (allf ? 2 : 0);
    }
}

__global__ __launch_bounds__(128, 16) void mha_fused_kernel(
    const float* __restrict__ ego,          // (B,1,D)
    const void*  __restrict__ mask,         // (B,N) bool, encoding detected
    const float* __restrict__ keys,         // (H,B,NK,DH)
    const float* __restrict__ value,        // (B,NK,DH)
    const float* __restrict__ W_q,          // (H,D,DH)
    float* __restrict__ out)                // (B,1,D): out[b][h*64+k]
{
    __shared__ float sc[NK + 1];        // scores -> p
    __shared__ float ego_sm[Dd];
    __shared__ float q_sm[DHh];
    __shared__ float red[128];
    __shared__ float wred[4];
    __shared__ float gmax_sm, ginv_sm;
    __shared__ unsigned char msk[NK + 1];

    const int bid  = blockIdx.x;
    const int b    = bid >> 3;      // b-major: 8 heads of same b co-resident -> value L2 reuse
    const int h    = bid & 7;
    const int t    = threadIdx.x;   // 0..127
    const int w    = t >> 5;        // 0..3
    const int lane = t & 31;

    // ---- stage mask row [b][1..N-1] into smem using detected encoding ----
    {
        const int mode = g_mask_mode;
        if (mode == 0) {
            const unsigned char* m8 = (const unsigned char*)mask + (size_t)b * Nn + 1;
            for (int n = t; n < NK; n += 128) msk[n] = m8[n];
        } else if (mode == 1) {
            const int* m32 = (const int*)mask + (size_t)b * Nn + 1;
            for (int n = t; n < NK; n += 128) msk[n] = (unsigned char)(m32[n] != 0);
        } else {
            const float* mf = (const float*)mask + (size_t)b * Nn + 1;
            for (int n = t; n < NK; n += 128) msk[n] = (unsigned char)(mf[n] != 0.0f);
        }
    }

    // ---- load ego row into smem ----
    for (int i = t; i < Dd; i += 128) ego_sm[i] = ego[b * Dd + i];
    __syncthreads();

    // ---- q[k] = sum_d ego[d] * W_q[h][d][k]  (2 threads per k, 256 d each) ----
    {
        const int k     = t & 63;
        const int dpart = t >> 6;                 // 0..1
        const float* wq = W_q + (size_t)h * Dd * DHh + k;
        float acc = 0.f;
        const int d0 = dpart * 256;
        #pragma unroll 4
        for (int d = d0; d < d0 + 256; ++d)
            acc += ego_sm[d] * wq[(size_t)d * DHh];
        red[t] = acc;
    }
    __syncthreads();
    if (t < DHh)
        q_sm[t] = red[t] + red[t + 64];
    __syncthreads();

    // ---- Phase 1: scores[n] = (q . keys[n]) / 8, masked ----
    // 8 lanes per row (each lane owns 32 contiguous bytes), 4 rows per warp-iter.
    const float* kbase = keys + (size_t)(h * Bq + b) * NK * DHh;

    const int rq   = lane >> 3;          // 0..3: row within quad
    const int kofs = (lane & 7) * 8;     // 8 floats per lane
    const float4 q0 = *(const float4*)(q_sm + kofs);
    const float4 q1 = *(const float4*)(q_sm + kofs + 4);

    float wmax = -3.0e38f;

    #pragma unroll 2
    for (int n0 = w * 4; n0 < NK; n0 += 16) {
        const int row = n0 + rq;
        const bool v  = row < NK;
        const float* kp = kbase + (size_t)row * DHh + kofs;
        float4 a0 = make_float4(0.f, 0.f, 0.f, 0.f);
        float4 a1 = make_float4(0.f, 0.f, 0.f, 0.f);
        if (v) {
            a0 = __ldcs((const float4*)kp);
            a1 = __ldcs((const float4*)(kp + 4));
        }
        float s = a0.x * q0.x + a0.y * q0.y + a0.z * q0.z + a0.w * q0.w
                + a1.x * q1.x + a1.y * q1.y + a1.z * q1.z + a1.w * q1.w;

        s += __shfl_xor_sync(0xffffffffu, s, 4);
        s += __shfl_xor_sync(0xffffffffu, s, 2);
        s += __shfl_xor_sync(0xffffffffu, s, 1);

        if (v && (lane & 7) == 0) {
            s *= 0.125f;
            if (!msk[row]) s = -1.0e30f;
            wmax = fmaxf(wmax, s);
            sc[row] = s;
        }
    }

    // ---- reduce max across warps ----
    #pragma unroll
    for (int o = 16; o; o >>= 1)
        wmax = fmaxf(wmax, __shfl_xor_sync(0xffffffffu, wmax, o));
    if (lane == 0) wred[w] = wmax;
    __syncthreads();
    if (t == 0) {
        float g = fmaxf(fmaxf(wred[0], wred[1]), fmaxf(wred[2], wred[3]));
        gmax_sm = g;
    }
    __syncthreads();
    const float gmax = gmax_sm;

    // ---- Phase 2: exponentiate in place + sum ----
    float lsum = 0.f;
    for (int n = t; n < NK; n += 128) {
        float e = __expf(sc[n] - gmax);
        sc[n] = e;
        lsum += e;
    }
    #pragma unroll
    for (int o = 16; o; o >>= 1)
        lsum += __shfl_xor_sync(0xffffffffu, lsum, o);
    if (lane == 0) wred[w] = lsum;
    __syncthreads();
    if (t == 0) {
        ginv_sm = 1.0f / (wred[0] + wred[1] + wred[2] + wred[3]);
    }
    __syncthreads();
    const float inv = ginv_sm;

    // ---- Phase 3: out[k] = inv * sum_n p[n] * value[b][n][k] ----
    {
        const int k    = t & 63;
        const int half = t >> 6;   // 0 or 1: n-parity
        const float* vp = value + (size_t)b * NK * DHh + k;
        float acc = 0.f;
        int n = half;
        #pragma unroll 2
        for (; n + 14 < NK; n += 16) {
            acc += sc[n]      * vp[(size_t)(n)      * DHh]
                 + sc[n + 2]  * vp[(size_t)(n + 2)  * DHh]
                 + sc[n + 4]  * vp[(size_t)(n + 4)  * DHh]
                 + sc[n + 6]  * vp[(size_t)(n + 6)  * DHh]
                 + sc[n + 8]  * vp[(size_t)(n + 8)  * DHh]
                 + sc[n + 10] * vp[(size_t)(n + 10) * DHh]
                 + sc[n + 12] * vp[(size_t)(n + 12) * DHh]
                 + sc[n + 14] * vp[(size_t)(n + 14) * DHh];
        }
        for (; n < NK; n += 2)
            acc += sc[n] * vp[(size_t)n * DHh];
        red[t] = acc;
    }
    __syncthreads();
    if (t < DHh) {
        float r = (red[t] + red[t + 64]) * inv;
        out[(size_t)b * Dd + h * DHh + t] = r;
    }
}

extern "C" void kernel_launch(void* const* d_in, const int* in_sizes, int n_in,
                              void* d_out, int out_size) {
    // Bind inputs by element count (all five are pairwise distinct).
    const float* ego   = nullptr;
    const void*  mask  = nullptr;
    const float* keys  = nullptr;
    const float* value = nullptr;
    const float* W_q   = nullptr;

    for (int i = 0; i < n_in; ++i) {
        switch (in_sizes[i]) {
            case Bq * Dd:                 ego   = (const float*)d_in[i]; break; // 131072
            case Bq * Nn:                 mask  = d_in[i];               break; // 524288
            case Hh * Bq * NK * DHh:      keys  = (const float*)d_in[i]; break; // 268173312
            case Bq * NK * DHh:           value = (const float*)d_in[i]; break; // 33521664
            case Hh * Dd * DHh:           W_q   = (const float*)d_in[i]; break; // 262144
            default: break;
        }
    }

    float* out = (float*)d_out;

    detect_mask_mode_kernel<<<1, 32>>>((const unsigned int*)mask);
    mha_fused_kernel<<<Hh * Bq, 128>>>(ego, mask, keys, value, W_q, out);
}

// round 6
// speedup vs baseline: 1.5352x; 1.5352x over previous
#include <cuda_runtime.h>
#include <cstdint>

#define Bq  256
#define Nn  2048
#define Dd  512
#define Hh  8
#define DHh 64
#define NK  2047            // N-1 keys per row

#define TILE    64          // rows per tile
#define STRIDE  68          // floats per row in smem (pad: conflict-free, 16B-multiple)
#define STAGES  3
#define NT      32          // ceil(2047/64)

// mask representation: 0 = int8, 1 = int32, 2 = float32
__device__ int g_mask_mode;

__global__ void detect_mask_mode_kernel(const unsigned int* __restrict__ mw) {
    __shared__ int a01, af;
    const int t = threadIdx.x;
    if (t == 0) { a01 = 1; af = 1; }
    __syncthreads();
    int l01 = 1, lf = 1;
    for (int i = t; i < 4096; i += blockDim.x) {
        unsigned v = mw[i];
        if (v != 0u && v != 1u) l01 = 0;
        if (v != 0u && v != 0x3F800000u) lf = 0;
    }
    if (!l01) atomicAnd(&a01, 0);
    if (!lf)  atomicAnd(&af, 0);
    __syncthreads();
    if (t == 0) g_mask_mode = a01 ? 1 : (af ? 2 : 0);
}

__device__ __forceinline__ unsigned int smem_u32(const void* p) {
    return (unsigned int)__cvta_generic_to_shared(p);
}
__device__ __forceinline__ void cp16(unsigned int dst, const void* src) {
    asm volatile("cp.async.cg.shared.global [%0], [%1], 16;" :: "r"(dst), "l"(src));
}
__device__ __forceinline__ void cp_commit() {
    asm volatile("cp.async.commit_group;" ::: "memory");
}
__device__ __forceinline__ void cp_wait2() {
    asm volatile("cp.async.wait_group 2;" ::: "memory");
}

// Shared layout (floats). All float4-read regions at 16B-aligned offsets.
#define OFF_KT    0
#define OFF_QSM   (STAGES * TILE * STRIDE)          // 13056 (%4==0)
#define OFF_SC    (OFF_QSM + DHh)                   // 13120 (%4==0)
#define OFF_EGO   (OFF_SC + 2048)                   // sc padded to 2048
#define OFF_RED   (OFF_EGO + Dd)
#define OFF_WRED  (OFF_RED + 256)
#define OFF_SCAL  (OFF_WRED + 8)
#define OFF_MSK   (OFF_SCAL + 4)                    // bytes start here
#define SMEM_FLOATS (OFF_MSK + (NK + 1 + 3) / 4 + 4)

__global__ __launch_bounds__(256, 3) void mha_fused_kernel(
    const float* __restrict__ ego,          // (B,1,D)
    const void*  __restrict__ mask,         // (B,N) bool, encoding detected
    const float* __restrict__ keys,         // (H,B,NK,DH)
    const float* __restrict__ value,        // (B,NK,DH)
    const float* __restrict__ W_q,          // (H,D,DH)
    float* __restrict__ out)                // (B,1,D)
{
    extern __shared__ float smem_dyn[];
    float* kt     = smem_dyn + OFF_KT;
    float* q_sm   = smem_dyn + OFF_QSM;
    float* sc     = smem_dyn + OFF_SC;
    float* ego_sm = smem_dyn + OFF_EGO;
    float* red    = smem_dyn + OFF_RED;
    float* wred   = smem_dyn + OFF_WRED;
    float* scal   = smem_dyn + OFF_SCAL;
    unsigned char* msk = (unsigned char*)(smem_dyn + OFF_MSK);

    const int bid  = blockIdx.x;
    const int b    = bid >> 3;     // b-major: 8 heads of same b near in time -> value L2 reuse
    const int h    = bid & 7;
    const int t    = threadIdx.x;  // 0..255
    const int w    = t >> 5;
    const int lane = t & 31;

    const float* kbase = keys  + (size_t)(h * Bq + b) * NK * DHh;
    const float* vbase = value + (size_t)b * NK * DHh;

    // tile copy: TILE rows x 64 floats = TILE*16 16B-chunks; 256 threads -> 4 each
    auto issue_tile = [&](const float* gbase, int tileIdx, int stage) {
        const int row0 = tileIdx * TILE;
        float* dstb = kt + stage * TILE * STRIDE;
        #pragma unroll
        for (int i = 0; i < (TILE * 16) / 256; ++i) {
            const int m   = t + i * 256;
            const int r   = m >> 4;
            const int c   = m & 15;
            const int row = row0 + r;
            if (row < NK)
                cp16(smem_u32(dstb + r * STRIDE + c * 4),
                     gbase + (size_t)row * DHh + c * 4);
        }
    };

    // ---- prologue: start K tiles 0,1 (async) ----
    issue_tile(kbase, 0, 0); cp_commit();
    issue_tile(kbase, 1, 1); cp_commit();

    // ---- overlap: mask staging + ego + q projection ----
    {
        const int mode = g_mask_mode;
        if (mode == 0) {
            const unsigned char* m8 = (const unsigned char*)mask + (size_t)b * Nn + 1;
            for (int n = t; n < NK; n += 256) msk[n] = m8[n];
        } else if (mode == 1) {
            const int* m32 = (const int*)mask + (size_t)b * Nn + 1;
            for (int n = t; n < NK; n += 256) msk[n] = (unsigned char)(m32[n] != 0);
        } else {
            const float* mf = (const float*)mask + (size_t)b * Nn + 1;
            for (int n = t; n < NK; n += 256) msk[n] = (unsigned char)(mf[n] != 0.0f);
        }
    }
    for (int i = t; i < Dd; i += 256) ego_sm[i] = ego[b * Dd + i];
    __syncthreads();
    {
        const int k     = t & 63;
        const int dpart = t >> 6;                 // 0..3, 128 d each
        const float* wq = W_q + (size_t)h * Dd * DHh + k;
        float acc = 0.f;
        const int d0 = dpart * 128;
        #pragma unroll 4
        for (int d = d0; d < d0 + 128; ++d)
            acc += ego_sm[d] * wq[(size_t)d * DHh];
        red[t] = acc;
    }
    __syncthreads();
    if (t < DHh) q_sm[t] = red[t] + red[t + 64] + red[t + 128] + red[t + 192];
    __syncthreads();

    // ---- Phase 1: pipelined score pass ----
    // warp w owns rows w*8+(lane&7) of the tile; lane quarter cq = lane>>3 owns 16 cols.
    const int rsub = lane & 7;
    const int cq   = lane >> 3;
    const float4 qa = *(const float4*)(q_sm + cq * 16);
    const float4 qb = *(const float4*)(q_sm + cq * 16 + 4);
    const float4 qc = *(const float4*)(q_sm + cq * 16 + 8);
    const float4 qd = *(const float4*)(q_sm + cq * 16 + 12);

    float wmax = -3.0e38f;

    for (int tl = 0; tl < NT; ++tl) {
        if (tl + 2 < NT) issue_tile(kbase, tl + 2, (tl + 2) % STAGES);
        cp_commit();                 // one group per iter (may be empty)
        cp_wait2();
        __syncthreads();

        const int   row0 = tl * TILE;
        const float* rp  = kt + (tl % STAGES) * TILE * STRIDE
                              + (w * 8 + rsub) * STRIDE + cq * 16;
        const float4 x0 = *(const float4*)(rp);
        const float4 x1 = *(const float4*)(rp + 4);
        const float4 x2 = *(const float4*)(rp + 8);
        const float4 x3 = *(const float4*)(rp + 12);

        float s = x0.x*qa.x + x0.y*qa.y + x0.z*qa.z + x0.w*qa.w
                + x1.x*qb.x + x1.y*qb.y + x1.z*qb.z + x1.w*qb.w
                + x2.x*qc.x + x2.y*qc.y + x2.z*qc.z + x2.w*qc.w
                + x3.x*qd.x + x3.y*qd.y + x3.z*qd.z + x3.w*qd.w;

        s += __shfl_xor_sync(0xffffffffu, s, 8);
        s += __shfl_xor_sync(0xffffffffu, s, 16);

        if (lane < 8) {
            const int row = row0 + w * 8 + lane;
            if (row < NK) {
                float sv = s * 0.125f;
                if (!msk[row]) sv = -1.0e30f;
                wmax = fmaxf(wmax, sv);
                sc[row] = sv;
            }
        }
        __syncthreads();
    }

    // ---- start V tiles 0,1 while we do the softmax reductions ----
    issue_tile(vbase, 0, 0); cp_commit();
    issue_tile(vbase, 1, 1); cp_commit();

    // ---- max reduce across warps ----
    #pragma unroll
    for (int o = 16; o; o >>= 1)
        wmax = fmaxf(wmax, __shfl_xor_sync(0xffffffffu, wmax, o));
    if (lane == 0) wred[w] = wmax;
    __syncthreads();
    if (t == 0) {
        float g = wred[0];
        #pragma unroll
        for (int i = 1; i < 8; ++i) g = fmaxf(g, wred[i]);
        scal[0] = g;
    }
    __syncthreads();
    const float gmax = scal[0];

    // ---- exponentiate + sum ----
    float lsum = 0.f;
    for (int n = t; n < NK; n += 256) {
        float e = __expf(sc[n] - gmax);
        sc[n] = e;
        lsum += e;
    }
    #pragma unroll
    for (int o = 16; o; o >>= 1)
        lsum += __shfl_xor_sync(0xffffffffu, lsum, o);
    if (lane == 0) wred[w] = lsum;
    __syncthreads();
    if (t == 0) {
        float ssum = 0.f;
        #pragma unroll
        for (int i = 0; i < 8; ++i) ssum += wred[i];
        scal[1] = 1.0f / ssum;
    }
    __syncthreads();
    const float inv = scal[1];

    // ---- Phase 3: pipelined P.V pass ----
    // thread (k = t&63, g = t>>6): rows r = g, g+4, ... of each tile.
    const int k3 = t & 63;
    const int g3 = t >> 6;
    float acc = 0.f;

    for (int tl = 0; tl < NT; ++tl) {
        if (tl + 2 < NT) issue_tile(vbase, tl + 2, (tl + 2) % STAGES);
        cp_commit();
        cp_wait2();
        __syncthreads();

        const int    row0 = tl * TILE;
        const float* vt   = kt + (tl % STAGES) * TILE * STRIDE;

        if (row0 + TILE <= NK) {
            #pragma unroll
            for (int r = g3; r < TILE; r += 4)
                acc += sc[row0 + r] * vt[r * STRIDE + k3];
        } else {
            for (int r = g3; r < TILE; r += 4) {
                const int row = row0 + r;
                if (row < NK) acc += sc[row] * vt[r * STRIDE + k3];
            }
        }
        __syncthreads();
    }

    red[t] = acc;
    __syncthreads();
    if (t < DHh) {
        float r = (red[t] + red[t + 64] + red[t + 128] + red[t + 192]) * inv;
        out[(size_t)b * Dd + h * DHh + t] = r;
    }
}

extern "C" void kernel_launch(void* const* d_in, const int* in_sizes, int n_in,
                              void* d_out, int out_size) {
    // Bind inputs by element count (all five pairwise distinct).
    const float* ego   = nullptr;
    const void*  mask  = nullptr;
    const float* keys  = nullptr;
    const float* value = nullptr;
    const float* W_q   = nullptr;

    for (int i = 0; i < n_in; ++i) {
        switch (in_sizes[i]) {
            case Bq * Dd:                 ego   = (const float*)d_in[i]; break; // 131072
            case Bq * Nn:                 mask  = d_in[i];               break; // 524288
            case Hh * Bq * NK * DHh:      keys  = (const float*)d_in[i]; break; // 268173312
            case Bq * NK * DHh:           value = (const float*)d_in[i]; break; // 33521664
            case Hh * Dd * DHh:           W_q   = (const float*)d_in[i]; break; // 262144
            default: break;
        }
    }

    float* out = (float*)d_out;

    const int smem_bytes = SMEM_FLOATS * 4;

    static bool attr_set = false;
    if (!attr_set) {
        cudaFuncSetAttribute(mha_fused_kernel,
                             cudaFuncAttributeMaxDynamicSharedMemorySize, smem_bytes);
        attr_set = true;
    }

    detect_mask_mode_kernel<<<1, 1024>>>((const unsigned int*)mask);
    mha_fused_kernel<<<Hh * Bq, 256, smem_bytes>>>(ego, mask, keys, value, W_q, out);
}

// round 7
// speedup vs baseline: 1.8680x; 1.2168x over previous
#include <cuda_runtime.h>
#include <cstdint>

#define Bq  256
#define Nn  2048
#define Dd  512
#define Hh  8
#define DHh 64
#define NK  2047            // N-1 keys per row
#define NCH 8               // n-chunks
#define CHR 256             // rows per chunk

// mask representation: 0 = int8, 1 = int32, 2 = float32
__device__ int g_mask_mode;

// scratch
__device__ float q_g[Hh * Bq * DHh];            // 512 KB
__device__ float part_m[Bq * NCH * Hh];         // 64 KB
__device__ float part_l[Bq * NCH * Hh];
__device__ float part_o[(size_t)Bq * NCH * Hh * DHh];  // 4 MB

__global__ void detect_mask_mode_kernel(const unsigned int* __restrict__ mw) {
    __shared__ int a01, af;
    const int t = threadIdx.x;
    if (t == 0) { a01 = 1; af = 1; }
    __syncthreads();
    int l01 = 1, lf = 1;
    for (int i = t; i < 4096; i += blockDim.x) {
        unsigned v = mw[i];
        if (v != 0u && v != 1u) l01 = 0;
        if (v != 0u && v != 0x3F800000u) lf = 0;
    }
    if (!l01) atomicAnd(&a01, 0);
    if (!lf)  atomicAnd(&af, 0);
    __syncthreads();
    if (t == 0) g_mask_mode = a01 ? 1 : (af ? 2 : 0);
}

// ---- q projection: grid 64 = (h, b-group of 32), 256 threads ----
__global__ __launch_bounds__(256) void q_proj_kernel(
    const float* __restrict__ ego, const float* __restrict__ W_q)
{
    __shared__ float ego8[8][512];   // 16 KB
    __shared__ float redq[2048];     // 8 KB
    const int h  = blockIdx.x >> 3;
    const int bg = blockIdx.x & 7;
    const int t  = threadIdx.x;
    const int k  = t & 63;
    const int dp = t >> 6;

    for (int blk = 0; blk < 4; ++blk) {
        const int bbase = bg * 32 + blk * 8;
        for (int i = t; i < 4096; i += 256)
            ego8[i >> 9][i & 511] = ego[(size_t)(bbase + (i >> 9)) * Dd + (i & 511)];
        __syncthreads();

        float acc[8] = {0, 0, 0, 0, 0, 0, 0, 0};
        const float* wq = W_q + (size_t)h * Dd * DHh + k;
        for (int d = dp * 128; d < dp * 128 + 128; ++d) {
            const float wv = wq[(size_t)d * DHh];
            #pragma unroll
            for (int j = 0; j < 8; ++j) acc[j] += ego8[j][d] * wv;
        }
        #pragma unroll
        for (int j = 0; j < 8; ++j) redq[j * 256 + t] = acc[j];
        __syncthreads();
        for (int i = t; i < 512; i += 256) {
            const int j = i >> 6, kk = i & 63;
            float s = redq[j * 256 + kk] + redq[j * 256 + 64 + kk]
                    + redq[j * 256 + 128 + kk] + redq[j * 256 + 192 + kk];
            q_g[(size_t)h * (Bq * DHh) + (size_t)(bbase + j) * DHh + kk] = s;
        }
        __syncthreads();
    }
}

// ---- main: grid 2048 = (b, chunk), 256 threads; warp w = head w ----
__global__ __launch_bounds__(256) void mha_chunk_kernel(
    const void*  __restrict__ mask,
    const float* __restrict__ keys,     // (H,B,NK,DH)
    const float* __restrict__ value)    // (B,NK,DH)
{
    __shared__ __align__(16) float q_sm[Hh * DHh];   // 512
    __shared__ float sc[Hh * CHR];                   // 8 KB
    __shared__ float red[4 * 512];                   // 8 KB
    __shared__ unsigned char msk_sm[CHR];

    const int bid  = blockIdx.x;
    const int b    = bid >> 3;
    const int c    = bid & 7;
    const int n0   = c * CHR;
    const int rows = (NK - n0 < CHR) ? (NK - n0) : CHR;
    const int t    = threadIdx.x;
    const int w    = t >> 5;        // head
    const int lane = t & 31;

    // stage q for all heads
    for (int i = t; i < Hh * DHh; i += 256)
        q_sm[i] = q_g[(size_t)(i >> 6) * (Bq * DHh) + (size_t)b * DHh + (i & 63)];

    // stage mask chunk
    {
        const int mode = g_mask_mode;
        if (mode == 0) {
            const unsigned char* m8 = (const unsigned char*)mask + (size_t)b * Nn + 1 + n0;
            for (int r = t; r < rows; r += 256) msk_sm[r] = m8[r];
        } else if (mode == 1) {
            const int* m32 = (const int*)mask + (size_t)b * Nn + 1 + n0;
            for (int r = t; r < rows; r += 256) msk_sm[r] = (unsigned char)(m32[r] != 0);
        } else {
            const float* mf = (const float*)mask + (size_t)b * Nn + 1 + n0;
            for (int r = t; r < rows; r += 256) msk_sm[r] = (unsigned char)(mf[r] != 0.0f);
        }
    }
    __syncthreads();

    // ---- Phase 1: warp w computes scores for head w over this chunk ----
    const int l8 = lane & 7;        // column-eighth
    const int rq = lane >> 3;       // row within quad
    const float* kb = keys + ((size_t)(w * Bq + b) * NK + n0) * DHh;
    const float4 qA = *(const float4*)(q_sm + w * DHh + l8 * 4);
    const float4 qB = *(const float4*)(q_sm + w * DHh + l8 * 4 + 32);

    float wm = -3.0e38f;

    #pragma unroll 2
    for (int it = 0; it < CHR / 4; ++it) {
        const int  r = it * 4 + rq;
        const bool v = r < rows;
        const float* kp = kb + (size_t)r * DHh + l8 * 4;
        float4 a  = make_float4(0.f, 0.f, 0.f, 0.f);
        float4 bb = make_float4(0.f, 0.f, 0.f, 0.f);
        if (v) {
            a  = __ldcs((const float4*)kp);        // bytes 0..127 of row (coalesced)
            bb = __ldcs((const float4*)(kp + 32)); // bytes 128..255
        }
        float s = a.x*qA.x + a.y*qA.y + a.z*qA.z + a.w*qA.w
                + bb.x*qB.x + bb.y*qB.y + bb.z*qB.z + bb.w*qB.w;
        s += __shfl_xor_sync(0xffffffffu, s, 1);
        s += __shfl_xor_sync(0xffffffffu, s, 2);
        s += __shfl_xor_sync(0xffffffffu, s, 4);
        if (v) {
            s *= 0.125f;
            if (!msk_sm[r]) s = -1.0e30f;
            wm = fmaxf(wm, s);
            if (l8 == 0) sc[w * CHR + r] = s;
        }
    }
    // warp max (groups of 8 already share values)
    wm = fmaxf(wm, __shfl_xor_sync(0xffffffffu, wm, 8));
    wm = fmaxf(wm, __shfl_xor_sync(0xffffffffu, wm, 16));
    const float m = wm;

    // ---- Phase 2: exp + sum (per warp/head) ----
    float ls = 0.f;
    for (int r = lane; r < rows; r += 32) {
        float p = __expf(sc[w * CHR + r] - m);
        sc[w * CHR + r] = p;
        ls += p;
    }
    #pragma unroll
    for (int o = 16; o; o >>= 1)
        ls += __shfl_xor_sync(0xffffffffu, ls, o);
    if (lane == 0) {
        part_m[bid * Hh + w] = m;
        part_l[bid * Hh + w] = ls;
    }
    __syncthreads();   // all heads' p ready

    // ---- Phase 3: o_partial[h][k] = sum_r p[h][r] * v[r][k] ----
    {
        const int k  = t & 63;
        const int q3 = t >> 6;
        const float* vp = value + ((size_t)b * NK + n0) * DHh + k;
        float acc[8] = {0, 0, 0, 0, 0, 0, 0, 0};
        if (rows == CHR) {
            #pragma unroll 4
            for (int r = q3; r < CHR; r += 4) {
                const float vv = __ldcs(vp + (size_t)r * DHh);
                #pragma unroll
                for (int h = 0; h < 8; ++h) acc[h] += sc[h * CHR + r] * vv;
            }
        } else {
            for (int r = q3; r < rows; r += 4) {
                const float vv = __ldcs(vp + (size_t)r * DHh);
                #pragma unroll
                for (int h = 0; h < 8; ++h) acc[h] += sc[h * CHR + r] * vv;
            }
        }
        #pragma unroll
        for (int h = 0; h < 8; ++h) red[q3 * 512 + h * 64 + k] = acc[h];
    }
    __syncthreads();
    for (int j = t; j < 512; j += 256) {
        float s = red[j] + red[512 + j] + red[1024 + j] + red[1536 + j];
        part_o[(size_t)bid * 512 + j] = s;   // j = h*64+k
    }
}

// ---- combine: grid 256 (b), 256 threads; warp w = head w ----
__global__ __launch_bounds__(256) void combine_kernel(float* __restrict__ out)
{
    const int b    = blockIdx.x;
    const int t    = threadIdx.x;
    const int w    = t >> 5;
    const int lane = t & 31;

    float mv[NCH], lv[NCH];
    #pragma unroll
    for (int c = 0; c < NCH; ++c) {
        mv[c] = part_m[(b * NCH + c) * Hh + w];
        lv[c] = part_l[(b * NCH + c) * Hh + w];
    }
    float M = mv[0];
    #pragma unroll
    for (int c = 1; c < NCH; ++c) M = fmaxf(M, mv[c]);
    float L = 0.f;
    float ws[NCH];
    #pragma unroll
    for (int c = 0; c < NCH; ++c) {
        ws[c] = __expf(mv[c] - M);
        L += lv[c] * ws[c];
    }
    const float invL = 1.0f / L;

    #pragma unroll
    for (int kk = 0; kk < 2; ++kk) {
        const int k = lane + kk * 32;
        float a = 0.f;
        #pragma unroll
        for (int c = 0; c < NCH; ++c)
            a += ws[c] * part_o[(size_t)(b * NCH + c) * 512 + w * 64 + k];
        out[(size_t)b * Dd + w * DHh + k] = a * invL;
    }
}

extern "C" void kernel_launch(void* const* d_in, const int* in_sizes, int n_in,
                              void* d_out, int out_size) {
    // Bind inputs by element count (all five pairwise distinct).
    const float* ego   = nullptr;
    const void*  mask  = nullptr;
    const float* keys  = nullptr;
    const float* value = nullptr;
    const float* W_q   = nullptr;

    for (int i = 0; i < n_in; ++i) {
        switch (in_sizes[i]) {
            case Bq * Dd:                 ego   = (const float*)d_in[i]; break; // 131072
            case Bq * Nn:                 mask  = d_in[i];               break; // 524288
            case Hh * Bq * NK * DHh:      keys  = (const float*)d_in[i]; break; // 268173312
            case Bq * NK * DHh:           value = (const float*)d_in[i]; break; // 33521664
            case Hh * Dd * DHh:           W_q   = (const float*)d_in[i]; break; // 262144
            default: break;
        }
    }

    float* out = (float*)d_out;

    detect_mask_mode_kernel<<<1, 1024>>>((const unsigned int*)mask);
    q_proj_kernel<<<64, 256>>>(ego, W_q);
    mha_chunk_kernel<<<Bq * NCH, 256>>>(mask, keys, value);
    combine_kernel<<<Bq, 256>>>(out);
}